// round 4
// baseline (speedup 1.0000x reference)
#include <cuda_runtime.h>

#define EMB   768
#define SEQL  256
#define NBATCH 256
#define NHEAD 12
#define HDIM  64
#define MTOT  (NBATCH * SEQL)   // 65536

// Scratch for Q/K/V projections, kept in X layout [w, s, e] so per-(w,h) tiles
// are contiguous 64-float rows. __device__ globals per harness rules.
__device__ float g_Q[(size_t)MTOT * EMB];
__device__ float g_K[(size_t)MTOT * EMB];
__device__ float g_V[(size_t)MTOT * EMB];

// ---------------------------------------------------------------------------
// C[m, n] = sum_k A[m,k] * W[n,k] + bias[n]     (A: [65536,768], W: [768,768])
// Block tile 128x128, K-tile 16, 256 threads, 8x8 per-thread register tile.
// ---------------------------------------------------------------------------
__global__ __launch_bounds__(256, 2)
void qkv_gemm_kernel(const float* __restrict__ A, const float* __restrict__ W,
                     const float* __restrict__ bias, int which)
{
    __shared__ __align__(16) float As[16][132];   // [k][m], padded
    __shared__ __align__(16) float Bs[16][132];   // [k][n], padded
    float* __restrict__ C = (which == 0) ? g_Q : (which == 1) ? g_K : g_V;

    const int t  = threadIdx.x;
    const int tx = t & 15;
    const int ty = t >> 4;
    const int m0 = blockIdx.y << 7;
    const int n0 = blockIdx.x << 7;

    float acc[8][8];
#pragma unroll
    for (int i = 0; i < 8; i++)
#pragma unroll
        for (int j = 0; j < 8; j++) acc[i][j] = 0.f;

    for (int k0 = 0; k0 < EMB; k0 += 16) {
        // 128 rows x 16 cols per tile = 512 float4 loads; 2 per thread each for A and W.
#pragma unroll
        for (int i = 0; i < 2; i++) {
            int f   = t + (i << 8);
            int row = f >> 2;
            int c4  = (f & 3) << 2;
            float4 va = *(const float4*)&A[(size_t)(m0 + row) * EMB + k0 + c4];
            As[c4 + 0][row] = va.x;
            As[c4 + 1][row] = va.y;
            As[c4 + 2][row] = va.z;
            As[c4 + 3][row] = va.w;
            float4 vb = *(const float4*)&W[(size_t)(n0 + row) * EMB + k0 + c4];
            Bs[c4 + 0][row] = vb.x;
            Bs[c4 + 1][row] = vb.y;
            Bs[c4 + 2][row] = vb.z;
            Bs[c4 + 3][row] = vb.w;
        }
        __syncthreads();
#pragma unroll
        for (int k = 0; k < 16; k++) {
            float ar[8], br[8];
            *(float4*)&ar[0] = *(const float4*)&As[k][(ty << 3) + 0];
            *(float4*)&ar[4] = *(const float4*)&As[k][(ty << 3) + 4];
            *(float4*)&br[0] = *(const float4*)&Bs[k][(tx << 3) + 0];
            *(float4*)&br[4] = *(const float4*)&Bs[k][(tx << 3) + 4];
#pragma unroll
            for (int i = 0; i < 8; i++)
#pragma unroll
                for (int j = 0; j < 8; j++)
                    acc[i][j] = fmaf(ar[i], br[j], acc[i][j]);
        }
        __syncthreads();
    }

    float bb[8];
#pragma unroll
    for (int j = 0; j < 8; j++) bb[j] = bias[n0 + (tx << 3) + j];
#pragma unroll
    for (int i = 0; i < 8; i++) {
        size_t row = (size_t)(m0 + (ty << 3) + i);
        float4 r0, r1;
        r0.x = acc[i][0] + bb[0]; r0.y = acc[i][1] + bb[1];
        r0.z = acc[i][2] + bb[2]; r0.w = acc[i][3] + bb[3];
        r1.x = acc[i][4] + bb[4]; r1.y = acc[i][5] + bb[5];
        r1.z = acc[i][6] + bb[6]; r1.w = acc[i][7] + bb[7];
        *(float4*)&C[row * EMB + n0 + (tx << 3) + 0] = r0;
        *(float4*)&C[row * EMB + n0 + (tx << 3) + 4] = r1;
    }
}

// ---------------------------------------------------------------------------
// Causal flash attention.
// Grid: (q_tile=4, head=12, batch=256). Block: 256 threads (16x16 of 4x4 frags).
// Per (w,h): seq=256, d=64. Q/K held d-major in smem (conflict-free float4
// reads), V k-major, P staged through smem between the two tile GEMMs.
// Dynamic smem: 4 * 64 * 68 * 4 = 69632 bytes.
// ---------------------------------------------------------------------------
#define ATT_SMEM (4 * 64 * 68 * 4)

__global__ __launch_bounds__(256)
void attn_kernel(float* __restrict__ Out)
{
    extern __shared__ __align__(16) float smem[];
    float* Qt = smem;                 // [d=64][r=64 (+4 pad)]   d-major
    float* Kt = smem + 64 * 68;       // [d=64][c=64 (+4 pad)]   d-major
    float* Vs = smem + 2 * 64 * 68;   // [k=64][dd=64 (+4 pad)]  k-major
    float* Ps = smem + 3 * 64 * 68;   // [q=64][k=64 (+4 pad)]

    const int t  = threadIdx.x;
    const int tx = t & 15;            // column block (4 wide)
    const int ty = t >> 4;            // row block (4 tall)
    const int qt = blockIdx.x;
    const int h  = blockIdx.y;
    const int w  = blockIdx.z;
    const size_t rbase = (size_t)w * SEQL;
    const int c0 = h * HDIM;

    // Load Q tile transposed (once per block).
#pragma unroll
    for (int i = 0; i < 4; i++) {
        int f = t + (i << 8);
        int r = f >> 4;
        int d = (f & 15) << 2;
        float4 v = *(const float4*)&g_Q[(rbase + (qt << 6) + r) * EMB + c0 + d];
        Qt[(d + 0) * 68 + r] = v.x;
        Qt[(d + 1) * 68 + r] = v.y;
        Qt[(d + 2) * 68 + r] = v.z;
        Qt[(d + 3) * 68 + r] = v.w;
    }

    float o[4][4];
    float mrow[4], lrow[4];
#pragma unroll
    for (int i = 0; i < 4; i++) {
        mrow[i] = -1e30f;
        lrow[i] = 0.f;
#pragma unroll
        for (int j = 0; j < 4; j++) o[i][j] = 0.f;
    }

    for (int kt = 0; kt <= qt; kt++) {
        // Load K (transposed) and V (natural) tiles.
#pragma unroll
        for (int i = 0; i < 4; i++) {
            int f = t + (i << 8);
            int r = f >> 4;
            int d = (f & 15) << 2;
            size_t g = (rbase + (kt << 6) + r) * EMB + c0 + d;
            float4 v = *(const float4*)&g_K[g];
            Kt[(d + 0) * 68 + r] = v.x;
            Kt[(d + 1) * 68 + r] = v.y;
            Kt[(d + 2) * 68 + r] = v.z;
            Kt[(d + 3) * 68 + r] = v.w;
            float4 vv = *(const float4*)&g_V[g];
            *(float4*)&Vs[r * 68 + d] = vv;
        }
        __syncthreads();

        // S = Q @ K^T (scaled)
        float s[4][4];
#pragma unroll
        for (int i = 0; i < 4; i++)
#pragma unroll
            for (int j = 0; j < 4; j++) s[i][j] = 0.f;

#pragma unroll 8
        for (int d = 0; d < 64; d++) {
            float4 qv = *(const float4*)&Qt[d * 68 + (ty << 2)];
            float4 kv = *(const float4*)&Kt[d * 68 + (tx << 2)];
            float qa[4] = {qv.x, qv.y, qv.z, qv.w};
            float ka[4] = {kv.x, kv.y, kv.z, kv.w};
#pragma unroll
            for (int i = 0; i < 4; i++)
#pragma unroll
                for (int j = 0; j < 4; j++)
                    s[i][j] = fmaf(qa[i], ka[j], s[i][j]);
        }
#pragma unroll
        for (int i = 0; i < 4; i++)
#pragma unroll
            for (int j = 0; j < 4; j++) s[i][j] *= 0.125f;   // 1/sqrt(64)

        if (kt == qt) {
#pragma unroll
            for (int i = 0; i < 4; i++)
#pragma unroll
                for (int j = 0; j < 4; j++)
                    if ((tx << 2) + j > (ty << 2) + i) s[i][j] = -1e30f;
        }

        // Online softmax (row stats reduced across the 16 tx threads per row).
#pragma unroll
        for (int i = 0; i < 4; i++) {
            float mt = fmaxf(fmaxf(s[i][0], s[i][1]), fmaxf(s[i][2], s[i][3]));
            mt = fmaxf(mt, __shfl_xor_sync(0xffffffffu, mt, 1));
            mt = fmaxf(mt, __shfl_xor_sync(0xffffffffu, mt, 2));
            mt = fmaxf(mt, __shfl_xor_sync(0xffffffffu, mt, 4));
            mt = fmaxf(mt, __shfl_xor_sync(0xffffffffu, mt, 8));
            float mn = fmaxf(mrow[i], mt);
            float rs = 0.f;
#pragma unroll
            for (int j = 0; j < 4; j++) {
                float p = __expf(s[i][j] - mn);
                s[i][j] = p;
                rs += p;
            }
            rs += __shfl_xor_sync(0xffffffffu, rs, 1);
            rs += __shfl_xor_sync(0xffffffffu, rs, 2);
            rs += __shfl_xor_sync(0xffffffffu, rs, 4);
            rs += __shfl_xor_sync(0xffffffffu, rs, 8);
            float al = __expf(mrow[i] - mn);
            lrow[i] = al * lrow[i] + rs;
            mrow[i] = mn;
#pragma unroll
            for (int j = 0; j < 4; j++) o[i][j] *= al;
            *(float4*)&Ps[((ty << 2) + i) * 68 + (tx << 2)] =
                make_float4(s[i][0], s[i][1], s[i][2], s[i][3]);
        }
        __syncthreads();

        // O += P @ V
#pragma unroll 4
        for (int k = 0; k < 64; k++) {
            float4 vv = *(const float4*)&Vs[k * 68 + (tx << 2)];
#pragma unroll
            for (int i = 0; i < 4; i++) {
                float p = Ps[((ty << 2) + i) * 68 + k];
                o[i][0] = fmaf(p, vv.x, o[i][0]);
                o[i][1] = fmaf(p, vv.y, o[i][1]);
                o[i][2] = fmaf(p, vv.z, o[i][2]);
                o[i][3] = fmaf(p, vv.w, o[i][3]);
            }
        }
        __syncthreads();
    }

    // Epilogue: normalize and store.
#pragma unroll
    for (int i = 0; i < 4; i++) {
        float inv = 1.0f / lrow[i];
        size_t q = rbase + (size_t)(qt << 6) + (ty << 2) + i;
        *(float4*)&Out[q * EMB + c0 + (tx << 2)] =
            make_float4(o[i][0] * inv, o[i][1] * inv, o[i][2] * inv, o[i][3] * inv);
    }
}

// ---------------------------------------------------------------------------

extern "C" void kernel_launch(void* const* d_in, const int* in_sizes, int n_in,
                              void* d_out, int out_size)
{
    const float* X  = (const float*)d_in[0];
    const float* Wq = (const float*)d_in[1];
    const float* bq = (const float*)d_in[2];
    const float* Wk = (const float*)d_in[3];
    const float* bk = (const float*)d_in[4];
    const float* Wv = (const float*)d_in[5];
    const float* bv = (const float*)d_in[6];
    float* Out = (float*)d_out;

    // Idempotent, deterministic, not a stream op — safe under graph capture.
    cudaFuncSetAttribute(attn_kernel,
                         cudaFuncAttributeMaxDynamicSharedMemorySize, ATT_SMEM);

    dim3 gg(EMB / 128, MTOT / 128);   // (6, 512)
    qkv_gemm_kernel<<<gg, 256>>>(X, Wq, bq, 0);
    qkv_gemm_kernel<<<gg, 256>>>(X, Wk, bk, 1);
    qkv_gemm_kernel<<<gg, 256>>>(X, Wv, bv, 2);

    attn_kernel<<<dim3(SEQL / 64, NHEAD, NBATCH), 256, ATT_SMEM>>>(Out);
}

// round 13
// speedup vs baseline: 1.7455x; 1.7455x over previous
#include <cuda_runtime.h>
#include <cuda_bf16.h>
#include <cstdint>

#define EMB    768
#define SEQL   256
#define NBATCH 256
#define NHEAD  12
#define HDIM   64
#define MTOT   (NBATCH * SEQL)   // 65536

// ---------------------------------------------------------------------------
// Device scratch (no allocs allowed)
// ---------------------------------------------------------------------------
__device__ float g_Q[(size_t)MTOT * EMB];
__device__ float g_K[(size_t)MTOT * EMB];
__device__ float g_V[(size_t)MTOT * EMB];
__device__ __nv_bfloat16 g_Ahi[(size_t)MTOT * EMB];
__device__ __nv_bfloat16 g_Alo[(size_t)MTOT * EMB];
__device__ __nv_bfloat16 g_Whi[3][EMB * EMB];
__device__ __nv_bfloat16 g_Wlo[3][EMB * EMB];

// ---------------------------------------------------------------------------
// PTX helpers (sm_103 baseline: mma.sync / ldmatrix / cp.async only)
// ---------------------------------------------------------------------------
__device__ __forceinline__ uint32_t smem_u32(const void* p) {
    uint32_t a;
    asm("{ .reg .u64 t; cvta.to.shared.u64 t, %1; cvt.u32.u64 %0, t; }"
        : "=r"(a) : "l"(p));
    return a;
}

__device__ __forceinline__ void cp_async16(uint32_t saddr, const void* g) {
    asm volatile("cp.async.cg.shared.global [%0], [%1], 16;" :: "r"(saddr), "l"(g));
}

#define CP_COMMIT() asm volatile("cp.async.commit_group;" ::: "memory")
#define CP_WAIT1()  asm volatile("cp.async.wait_group 1;" ::: "memory")

#define LDSM_X4(r0, r1, r2, r3, addr) \
    asm volatile("ldmatrix.sync.aligned.m8n8.x4.shared.b16 {%0,%1,%2,%3}, [%4];" \
                 : "=r"(r0), "=r"(r1), "=r"(r2), "=r"(r3) : "r"(addr))

#define MMA16816(c, a0, a1, a2, a3, b0, b1) \
    asm volatile("mma.sync.aligned.m16n8k16.row.col.f32.bf16.bf16.f32 " \
                 "{%0,%1,%2,%3}, {%4,%5,%6,%7}, {%8,%9}, {%0,%1,%2,%3};" \
                 : "+f"((c)[0]), "+f"((c)[1]), "+f"((c)[2]), "+f"((c)[3]) \
                 : "r"(a0), "r"(a1), "r"(a2), "r"(a3), "r"(b0), "r"(b1))

// ---------------------------------------------------------------------------
// Split fp32 -> (bf16 hi, bf16 lo) so that hi + lo == x within ~2^-17.
// ---------------------------------------------------------------------------
__device__ __forceinline__ void split4(float4 v, uint2& ph, uint2& pl) {
    float a[4] = {v.x, v.y, v.z, v.w};
    uint32_t hh[4], ll[4];
#pragma unroll
    for (int j = 0; j < 4; j++) {
        __nv_bfloat16 h = __float2bfloat16(a[j]);
        __nv_bfloat16 l = __float2bfloat16(a[j] - __bfloat162float(h));
        hh[j] = (uint32_t)__bfloat16_as_ushort(h);
        ll[j] = (uint32_t)__bfloat16_as_ushort(l);
    }
    ph = make_uint2(hh[0] | (hh[1] << 16), hh[2] | (hh[3] << 16));
    pl = make_uint2(ll[0] | (ll[1] << 16), ll[2] | (ll[3] << 16));
}

__global__ void split_x_kernel(const float* __restrict__ X) {
    size_t i = ((size_t)blockIdx.x * blockDim.x + threadIdx.x) * 4;
    float4 v = *(const float4*)(X + i);
    uint2 ph, pl;
    split4(v, ph, pl);
    *(uint2*)(g_Ahi + i) = ph;
    *(uint2*)(g_Alo + i) = pl;
}

__global__ void split_w_kernel(const float* __restrict__ Wq,
                               const float* __restrict__ Wk,
                               const float* __restrict__ Wv) {
    int which = blockIdx.y;
    const float* src = (which == 0) ? Wq : (which == 1) ? Wk : Wv;
    size_t i = ((size_t)blockIdx.x * blockDim.x + threadIdx.x) * 4;
    float4 v = *(const float4*)(src + i);
    uint2 ph, pl;
    split4(v, ph, pl);
    *(uint2*)(&g_Whi[which][0] + i) = ph;
    *(uint2*)(&g_Wlo[which][0] + i) = pl;
}

// ---------------------------------------------------------------------------
// mma.sync bf16 QKV GEMM with hi/lo compensation (3 passes fused per k-step):
//   C[m,n] = sum_k (Ahi+Alo)[m,k]*(Whi+Wlo)[n,k] + bias[n]  (drop lo*lo)
// Block 128x128, 8 warps (4x2), warp tile 32x64, K staged 32 via 3-deep
// cp.async pipeline. smem per stage: 4 tensors * 128 rows * 80B = 40960B.
// grid = (512, 6, 3), block = 256.
// ---------------------------------------------------------------------------
#define PITCH   80
#define TEN_SZ  (128 * PITCH)     // 10240
#define STAGE_SZ (4 * TEN_SZ)     // 40960
#define NSTAGE  3
#define KSTEPS  (EMB / 32)        // 24
#define GEMM_SMEM (NSTAGE * STAGE_SZ)   // 122880

__global__ void __launch_bounds__(256, 1)
qkv_mma_gemm(const float* __restrict__ bq, const float* __restrict__ bk,
             const float* __restrict__ bv)
{
    extern __shared__ char smem[];
    const uint32_t sb = smem_u32(smem);

    const int which = blockIdx.z;
    const float* bias = (which == 0) ? bq : (which == 1) ? bk : bv;
    float* Cout = (which == 0) ? g_Q : (which == 1) ? g_K : g_V;
    const __nv_bfloat16* Whi = g_Whi[which];
    const __nv_bfloat16* Wlo = g_Wlo[which];

    const int t    = threadIdx.x;
    const int lane = t & 31;
    const int w    = t >> 5;
    const int wm   = (w & 3) << 5;    // warp m offset within block: 0,32,64,96
    const int wn   = (w >> 2) << 6;   // warp n offset within block: 0,64
    const int m0   = blockIdx.x << 7;
    const int n0   = blockIdx.y << 7;

    // Loader mapping: thread t loads row lr, two 16B chunks at byte col lcb.
    const int lr  = t >> 1;
    const int lcb = (t & 1) << 5;                    // 0 or 32 bytes
    const int lce = (t & 1) << 4;                    // 0 or 16 bf16 elems
    const __nv_bfloat16* gAh = g_Ahi + (size_t)(m0 + lr) * EMB + lce;
    const __nv_bfloat16* gAl = g_Alo + (size_t)(m0 + lr) * EMB + lce;
    const __nv_bfloat16* gBh = Whi   + (size_t)(n0 + lr) * EMB + lce;
    const __nv_bfloat16* gBl = Wlo   + (size_t)(n0 + lr) * EMB + lce;
    const uint32_t soff = (uint32_t)(lr * PITCH + lcb);

    // ldmatrix per-thread address components.
    const uint32_t a_row  = (uint32_t)(lane & 15);
    const uint32_t a_koff = (uint32_t)((lane >> 4) << 4);            // bytes
    const uint32_t b_row  = (uint32_t)(((lane >> 4) << 3) + (lane & 7));
    const uint32_t b_koff = (uint32_t)(((lane >> 3) & 1) << 4);      // bytes

    float c[2][8][4];
#pragma unroll
    for (int mi = 0; mi < 2; mi++)
#pragma unroll
        for (int nj = 0; nj < 8; nj++)
#pragma unroll
            for (int q = 0; q < 4; q++) c[mi][nj][q] = 0.f;

    // ---- pipeline prologue: fill stages 0..NSTAGE-2
#pragma unroll
    for (int s = 0; s < NSTAGE - 1; s++) {
        const uint32_t s0 = sb + s * STAGE_SZ;
        const int kk = s * 32;
        cp_async16(s0 + soff,                   gAh + kk);
        cp_async16(s0 + soff + 16,              gAh + kk + 8);
        cp_async16(s0 + TEN_SZ + soff,          gAl + kk);
        cp_async16(s0 + TEN_SZ + soff + 16,     gAl + kk + 8);
        cp_async16(s0 + 2 * TEN_SZ + soff,      gBh + kk);
        cp_async16(s0 + 2 * TEN_SZ + soff + 16, gBh + kk + 8);
        cp_async16(s0 + 3 * TEN_SZ + soff,      gBl + kk);
        cp_async16(s0 + 3 * TEN_SZ + soff + 16, gBl + kk + 8);
        CP_COMMIT();
    }

    for (int ks = 0; ks < KSTEPS; ks++) {
        CP_WAIT1();
        __syncthreads();

        // Issue loads for stage ks+NSTAGE-1 (buffer freed at iteration ks-1).
        const int nxt = ks + NSTAGE - 1;
        if (nxt < KSTEPS) {
            const uint32_t s0 = sb + (nxt % NSTAGE) * STAGE_SZ;
            const int kk = nxt * 32;
            cp_async16(s0 + soff,                   gAh + kk);
            cp_async16(s0 + soff + 16,              gAh + kk + 8);
            cp_async16(s0 + TEN_SZ + soff,          gAl + kk);
            cp_async16(s0 + TEN_SZ + soff + 16,     gAl + kk + 8);
            cp_async16(s0 + 2 * TEN_SZ + soff,      gBh + kk);
            cp_async16(s0 + 2 * TEN_SZ + soff + 16, gBh + kk + 8);
            cp_async16(s0 + 3 * TEN_SZ + soff,      gBl + kk);
            cp_async16(s0 + 3 * TEN_SZ + soff + 16, gBl + kk + 8);
        }
        CP_COMMIT();

        // ---- compute stage ks%NSTAGE: two k16 halves
        const uint32_t sA = sb + (ks % NSTAGE) * STAGE_SZ;
        const uint32_t sB = sA + 2 * TEN_SZ;
#pragma unroll
        for (int half = 0; half < 2; half++) {
            const uint32_t kb = (uint32_t)(half << 5);   // 16 bf16 = 32 bytes

            uint32_t ah[2][4], al[2][4];
#pragma unroll
            for (int mi = 0; mi < 2; mi++) {
                uint32_t ra = sA + (wm + (mi << 4) + a_row) * PITCH + kb + a_koff;
                LDSM_X4(ah[mi][0], ah[mi][1], ah[mi][2], ah[mi][3], ra);
                LDSM_X4(al[mi][0], al[mi][1], al[mi][2], al[mi][3], ra + TEN_SZ);
            }
            // B is [n][k] K-contiguous == the "col" operand layout for
            // mma.row.col, so the b-fragment comes from NON-transposed
            // ldmatrix with row addresses pointing at the n-rows.
            uint32_t bh[8][2], bl[8][2];
#pragma unroll
            for (int nj2 = 0; nj2 < 4; nj2++) {
                uint32_t rb = sB + (wn + (nj2 << 4) + b_row) * PITCH + kb + b_koff;
                LDSM_X4(bh[nj2 * 2][0], bh[nj2 * 2][1],
                        bh[nj2 * 2 + 1][0], bh[nj2 * 2 + 1][1], rb);
                LDSM_X4(bl[nj2 * 2][0], bl[nj2 * 2][1],
                        bl[nj2 * 2 + 1][0], bl[nj2 * 2 + 1][1], rb + TEN_SZ);
            }
#pragma unroll
            for (int mi = 0; mi < 2; mi++)
#pragma unroll
                for (int nj = 0; nj < 8; nj++) {
                    MMA16816(c[mi][nj], ah[mi][0], ah[mi][1], ah[mi][2], ah[mi][3],
                             bh[nj][0], bh[nj][1]);
                    MMA16816(c[mi][nj], ah[mi][0], ah[mi][1], ah[mi][2], ah[mi][3],
                             bl[nj][0], bl[nj][1]);
                    MMA16816(c[mi][nj], al[mi][0], al[mi][1], al[mi][2], al[mi][3],
                             bh[nj][0], bh[nj][1]);
                }
        }
    }

    // ---- epilogue: +bias, store fp32
#pragma unroll
    for (int mi = 0; mi < 2; mi++) {
        const int row = m0 + wm + (mi << 4) + (lane >> 2);
        float* p0 = Cout + (size_t)row * EMB + n0 + wn;
        float* p1 = p0 + (size_t)8 * EMB;
#pragma unroll
        for (int nj = 0; nj < 8; nj++) {
            const int col = (nj << 3) + ((lane & 3) << 1);
            const float b0v = bias[n0 + wn + col];
            const float b1v = bias[n0 + wn + col + 1];
            *(float2*)(p0 + col) = make_float2(c[mi][nj][0] + b0v, c[mi][nj][1] + b1v);
            *(float2*)(p1 + col) = make_float2(c[mi][nj][2] + b0v, c[mi][nj][3] + b1v);
        }
    }
}

// ---------------------------------------------------------------------------
// Causal flash attention (unchanged from R4 baseline — known good, 967us).
// ---------------------------------------------------------------------------
#define ATT_SMEM (4 * 64 * 68 * 4)

__global__ __launch_bounds__(256)
void attn_kernel(float* __restrict__ Out)
{
    extern __shared__ __align__(16) float asmem[];
    float* Qt = asmem;
    float* Kt = asmem + 64 * 68;
    float* Vs = asmem + 2 * 64 * 68;
    float* Ps = asmem + 3 * 64 * 68;

    const int t  = threadIdx.x;
    const int tx = t & 15;
    const int ty = t >> 4;
    const int qt = blockIdx.x;
    const int h  = blockIdx.y;
    const int w  = blockIdx.z;
    const size_t rbase = (size_t)w * SEQL;
    const int c0 = h * HDIM;

#pragma unroll
    for (int i = 0; i < 4; i++) {
        int f = t + (i << 8);
        int r = f >> 4;
        int d = (f & 15) << 2;
        float4 v = *(const float4*)&g_Q[(rbase + (qt << 6) + r) * EMB + c0 + d];
        Qt[(d + 0) * 68 + r] = v.x;
        Qt[(d + 1) * 68 + r] = v.y;
        Qt[(d + 2) * 68 + r] = v.z;
        Qt[(d + 3) * 68 + r] = v.w;
    }

    float o[4][4];
    float mrow[4], lrow[4];
#pragma unroll
    for (int i = 0; i < 4; i++) {
        mrow[i] = -1e30f;
        lrow[i] = 0.f;
#pragma unroll
        for (int j = 0; j < 4; j++) o[i][j] = 0.f;
    }

    for (int kt = 0; kt <= qt; kt++) {
#pragma unroll
        for (int i = 0; i < 4; i++) {
            int f = t + (i << 8);
            int r = f >> 4;
            int d = (f & 15) << 2;
            size_t g = (rbase + (kt << 6) + r) * EMB + c0 + d;
            float4 v = *(const float4*)&g_K[g];
            Kt[(d + 0) * 68 + r] = v.x;
            Kt[(d + 1) * 68 + r] = v.y;
            Kt[(d + 2) * 68 + r] = v.z;
            Kt[(d + 3) * 68 + r] = v.w;
            float4 vv = *(const float4*)&g_V[g];
            *(float4*)&Vs[r * 68 + d] = vv;
        }
        __syncthreads();

        float s[4][4];
#pragma unroll
        for (int i = 0; i < 4; i++)
#pragma unroll
            for (int j = 0; j < 4; j++) s[i][j] = 0.f;

#pragma unroll 8
        for (int d = 0; d < 64; d++) {
            float4 qv = *(const float4*)&Qt[d * 68 + (ty << 2)];
            float4 kv = *(const float4*)&Kt[d * 68 + (tx << 2)];
            float qa[4] = {qv.x, qv.y, qv.z, qv.w};
            float ka[4] = {kv.x, kv.y, kv.z, kv.w};
#pragma unroll
            for (int i = 0; i < 4; i++)
#pragma unroll
                for (int j = 0; j < 4; j++)
                    s[i][j] = fmaf(qa[i], ka[j], s[i][j]);
        }
#pragma unroll
        for (int i = 0; i < 4; i++)
#pragma unroll
            for (int j = 0; j < 4; j++) s[i][j] *= 0.125f;

        if (kt == qt) {
#pragma unroll
            for (int i = 0; i < 4; i++)
#pragma unroll
                for (int j = 0; j < 4; j++)
                    if ((tx << 2) + j > (ty << 2) + i) s[i][j] = -1e30f;
        }

#pragma unroll
        for (int i = 0; i < 4; i++) {
            float mt = fmaxf(fmaxf(s[i][0], s[i][1]), fmaxf(s[i][2], s[i][3]));
            mt = fmaxf(mt, __shfl_xor_sync(0xffffffffu, mt, 1));
            mt = fmaxf(mt, __shfl_xor_sync(0xffffffffu, mt, 2));
            mt = fmaxf(mt, __shfl_xor_sync(0xffffffffu, mt, 4));
            mt = fmaxf(mt, __shfl_xor_sync(0xffffffffu, mt, 8));
            float mn = fmaxf(mrow[i], mt);
            float rs = 0.f;
#pragma unroll
            for (int j = 0; j < 4; j++) {
                float pp = __expf(s[i][j] - mn);
                s[i][j] = pp;
                rs += pp;
            }
            rs += __shfl_xor_sync(0xffffffffu, rs, 1);
            rs += __shfl_xor_sync(0xffffffffu, rs, 2);
            rs += __shfl_xor_sync(0xffffffffu, rs, 4);
            rs += __shfl_xor_sync(0xffffffffu, rs, 8);
            float al = __expf(mrow[i] - mn);
            lrow[i] = al * lrow[i] + rs;
            mrow[i] = mn;
#pragma unroll
            for (int j = 0; j < 4; j++) o[i][j] *= al;
            *(float4*)&Ps[((ty << 2) + i) * 68 + (tx << 2)] =
                make_float4(s[i][0], s[i][1], s[i][2], s[i][3]);
        }
        __syncthreads();

#pragma unroll 4
        for (int k = 0; k < 64; k++) {
            float4 vv = *(const float4*)&Vs[k * 68 + (tx << 2)];
#pragma unroll
            for (int i = 0; i < 4; i++) {
                float pp = Ps[((ty << 2) + i) * 68 + k];
                o[i][0] = fmaf(pp, vv.x, o[i][0]);
                o[i][1] = fmaf(pp, vv.y, o[i][1]);
                o[i][2] = fmaf(pp, vv.z, o[i][2]);
                o[i][3] = fmaf(pp, vv.w, o[i][3]);
            }
        }
        __syncthreads();
    }

#pragma unroll
    for (int i = 0; i < 4; i++) {
        float inv = 1.0f / lrow[i];
        size_t q = rbase + (size_t)(qt << 6) + (ty << 2) + i;
        *(float4*)&Out[q * EMB + c0 + (tx << 2)] =
            make_float4(o[i][0] * inv, o[i][1] * inv, o[i][2] * inv, o[i][3] * inv);
    }
}

// ---------------------------------------------------------------------------

extern "C" void kernel_launch(void* const* d_in, const int* in_sizes, int n_in,
                              void* d_out, int out_size)
{
    const float* X  = (const float*)d_in[0];
    const float* Wq = (const float*)d_in[1];
    const float* bq = (const float*)d_in[2];
    const float* Wk = (const float*)d_in[3];
    const float* bk = (const float*)d_in[4];
    const float* Wv = (const float*)d_in[5];
    const float* bv = (const float*)d_in[6];
    float* Out = (float*)d_out;

    cudaFuncSetAttribute(attn_kernel,
                         cudaFuncAttributeMaxDynamicSharedMemorySize, ATT_SMEM);
    cudaFuncSetAttribute(qkv_mma_gemm,
                         cudaFuncAttributeMaxDynamicSharedMemorySize, GEMM_SMEM);

    // hi/lo bf16 splits
    split_x_kernel<<<(MTOT * EMB) / 1024, 256>>>(X);
    split_w_kernel<<<dim3((EMB * EMB) / 1024, 3), 256>>>(Wq, Wk, Wv);

    // tensor-core QKV projections (all three in one grid)
    qkv_mma_gemm<<<dim3(MTOT / 128, EMB / 128, 3), 256, GEMM_SMEM>>>(bq, bk, bv);

    // fp32 flash attention
    attn_kernel<<<dim3(SEQL / 64, NHEAD, NBATCH), 256, ATT_SMEM>>>(Out);
}